// round 5
// baseline (speedup 1.0000x reference)
#include <cuda_runtime.h>
#include <cuda_fp16.h>
#include <cstdint>

// Problem sizes (fixed by setup_inputs)
#define NN 8192   // nodes
#define DD 128    // embedding dim
#define EE 4096   // hyperedges
#define KK 8192   // reduction dim of the big GEMMs
#define LN_EPS 1e-5f

// ---------------- GEMM config: 128x128 CTA tile, split-K ---------------------
#define KTILE 64                        // halfs per k-chunk = 128 B rows
#define STAGES 4
#define A_TILE_B (128 * 128)            // 16 KB (128 m-rows x 128B)
#define B_TILE_B (128 * 128)            // 16 KB (128 n-rows / 2 panels)
#define STAGE_B (A_TILE_B + B_TILE_B)   // 32 KB
#define GEMM_SMEM (STAGES * STAGE_B)    // 128 KB

// ---------------- scratch (device globals; no allocation allowed) ------------
__device__ __half g_Th [(size_t)NN * NN];     // T fp16             128 MB
__device__ __half g_hH [(size_t)NN * EE];     // h fp16 [N,E]        64 MB
__device__ __half g_Xh [(size_t)DD * NN];     // x^T fp16             2 MB
__device__ __half g_Tbh[(size_t)DD * NN];     // t^T fp16             2 MB
__device__ float  g_P  [(size_t)2 * DD * NN]; // fp32 partials        8 MB
__device__ float  g_S  [(size_t)4 * DD * EE]; // final partials       8 MB
__device__ float  g_counts[EE];

// ---------------- helpers ----------------
__device__ __forceinline__ uint32_t h2u(__half2 h) {
  uint32_t u;
  *reinterpret_cast<__half2*>(&u) = h;
  return u;
}
__device__ __forceinline__ uint32_t smem_u32(const void* p) {
  uint32_t a;
  asm("{ .reg .u64 t; cvta.to.shared.u64 t, %1; cvt.u32.u64 %0, t; }" : "=r"(a) : "l"(p));
  return a;
}
__device__ __forceinline__ uint32_t swz(uint32_t b) { return b ^ ((b >> 3) & 0x70); }
__device__ __forceinline__ void cp_async16(uint32_t dst, const void* src) {
  asm volatile("cp.async.cg.shared.global [%0], [%1], 16;" :: "r"(dst), "l"(src));
}
__device__ __forceinline__ void ldmatrix_x4(uint32_t& r0, uint32_t& r1, uint32_t& r2,
                                            uint32_t& r3, uint32_t addr) {
  asm volatile("ldmatrix.sync.aligned.m8n8.x4.shared.b16 {%0,%1,%2,%3}, [%4];"
               : "=r"(r0), "=r"(r1), "=r"(r2), "=r"(r3) : "r"(addr));
}
__device__ __forceinline__ void ldmatrix_x4t(uint32_t& r0, uint32_t& r1, uint32_t& r2,
                                             uint32_t& r3, uint32_t addr) {
  asm volatile("ldmatrix.sync.aligned.m8n8.x4.trans.shared.b16 {%0,%1,%2,%3}, [%4];"
               : "=r"(r0), "=r"(r1), "=r"(r2), "=r"(r3) : "r"(addr));
}
__device__ __forceinline__ void mma16816(float* c, uint32_t a0, uint32_t a1, uint32_t a2,
                                         uint32_t a3, uint32_t b0, uint32_t b1) {
  asm volatile(
      "mma.sync.aligned.m16n8k16.row.col.f32.f16.f16.f32 "
      "{%0,%1,%2,%3}, {%4,%5,%6,%7}, {%8,%9}, {%0,%1,%2,%3};"
      : "+f"(c[0]), "+f"(c[1]), "+f"(c[2]), "+f"(c[3])
      : "r"(a0), "r"(a1), "r"(a2), "r"(a3), "r"(b0), "r"(b1));
}

// Warp layout: 8 warps, wm = (wid&3)*32 (M), wn = (wid>>2)*64 (N).
// acc[mt 0..1][nt 0..7][4] covers 32m x 64n per warp.

// ====== GEMM NT: Cpart[128,128-tile] = A[128,Kslice] @ B[ntile,Kslice]^T =====
// B K-major (row n contiguous along k). Output fp32 partial slab blockIdx.y.
__global__ __launch_bounds__(256, 1)
void gemm_nt2(const __half* __restrict__ A, const __half* __restrict__ B,
              int kIters, float* __restrict__ Cp, int ldC, size_t slabStride) {
  extern __shared__ char smem[];
  uint32_t sb = smem_u32(smem);
  const int tid = threadIdx.x;
  const int wid = tid >> 5, lane = tid & 31;
  const int n0 = blockIdx.x * 128;
  const int kOff = blockIdx.y * kIters;
  const int wm = (wid & 3) * 32;
  const int wn = (wid >> 2) * 64;

  const int lj = lane >> 3, lr = lane & 7;
  int aRow[2];
  aRow[0] = wm + ((lj & 1) << 3) + lr;
  aRow[1] = aRow[0] + 16;
  const int aChO = lj >> 1;
  const int bRowBase = wn + ((lj >> 1) << 3) + lr;
  const int bChO = lj & 1;

  float acc[2][8][4];
#pragma unroll
  for (int i = 0; i < 2; i++)
#pragma unroll
    for (int j = 0; j < 8; j++)
#pragma unroll
      for (int q = 0; q < 4; q++) acc[i][j][q] = 0.f;

  auto load_stage = [&](int s, int kc) {
    uint32_t base = sb + s * STAGE_B;
    const __half* Ak = A + (size_t)kc * KTILE;
    const __half* Bk = B + (size_t)n0 * KK + (size_t)kc * KTILE;
#pragma unroll
    for (int j = 0; j < 8; j++) {
      int idx = tid + j * 256;
      int c = idx & 7;
      int row = (idx >> 3) & 127;
      if (idx < 1024) {
        cp_async16(base + swz(row * 128 + c * 16), Ak + (size_t)row * KK + c * 8);
      } else {
        cp_async16(base + A_TILE_B + swz(row * 128 + c * 16),
                   Bk + (size_t)row * KK + c * 8);
      }
    }
  };

  auto compute_stage = [&](int s) {
    uint32_t abase = sb + s * STAGE_B;
    uint32_t bbase = abase + A_TILE_B;
#pragma unroll
    for (int ks = 0; ks < 4; ks++) {
      const int kc2 = ks * 2;
      uint32_t a[2][4], b[4][4];
#pragma unroll
      for (int mt = 0; mt < 2; mt++) {
        uint32_t addr = abase + aRow[mt] * 128 + (((kc2 + aChO) ^ (aRow[mt] & 7)) << 4);
        ldmatrix_x4(a[mt][0], a[mt][1], a[mt][2], a[mt][3], addr);
      }
#pragma unroll
      for (int p = 0; p < 4; p++) {
        int brow = bRowBase + p * 16;
        uint32_t addr = bbase + brow * 128 + (((kc2 + bChO) ^ (brow & 7)) << 4);
        ldmatrix_x4(b[p][0], b[p][1], b[p][2], b[p][3], addr);
      }
#pragma unroll
      for (int mt = 0; mt < 2; mt++)
#pragma unroll
        for (int nt = 0; nt < 8; nt++) {
          uint32_t b0 = b[nt >> 1][(nt & 1) ? 2 : 0];
          uint32_t b1 = b[nt >> 1][(nt & 1) ? 3 : 1];
          mma16816(acc[mt][nt], a[mt][0], a[mt][1], a[mt][2], a[mt][3], b0, b1);
        }
    }
  };

#pragma unroll
  for (int s = 0; s < STAGES - 1; s++) {
    load_stage(s, kOff + s);
    asm volatile("cp.async.commit_group;" ::: "memory");
  }
  for (int it = 0; it < kIters; ++it) {
    int s = it & (STAGES - 1);
    asm volatile("cp.async.wait_group %0;" :: "n"(STAGES - 2) : "memory");
    __syncthreads();
    int pf = it + STAGES - 1;
    if (pf < kIters) load_stage(pf & (STAGES - 1), kOff + pf);
    asm volatile("cp.async.commit_group;" ::: "memory");
    compute_stage(s);
  }

  float* C = Cp + (size_t)blockIdx.y * slabStride;
  const int g = lane >> 2, tg = lane & 3;
#pragma unroll
  for (int mt = 0; mt < 2; mt++)
#pragma unroll
    for (int nt = 0; nt < 8; nt++) {
      int row0 = wm + mt * 16 + g;
      int col0 = n0 + wn + nt * 8 + tg * 2;
      *(float2*)(C + (size_t)row0 * ldC + col0) =
          make_float2(acc[mt][nt][0], acc[mt][nt][1]);
      *(float2*)(C + (size_t)(row0 + 8) * ldC + col0) =
          make_float2(acc[mt][nt][2], acc[mt][nt][3]);
    }
}

// ====== GEMM TN: Cpart[128,128-tile] = A[128,Kslice] @ B[Kslice,ntile] =======
// B N-major [k][n] (trans ldmatrix). Two 64-col panels per stage in smem.
__global__ __launch_bounds__(256, 1)
void gemm_tn2(const __half* __restrict__ A, const __half* __restrict__ B, int ldB,
              int kIters, float* __restrict__ Cp, int ldC, size_t slabStride) {
  extern __shared__ char smem[];
  uint32_t sb = smem_u32(smem);
  const int tid = threadIdx.x;
  const int wid = tid >> 5, lane = tid & 31;
  const int n0 = blockIdx.x * 128;
  const int kOff = blockIdx.y * kIters;
  const int wm = (wid & 3) * 32;
  const int wn = (wid >> 2) * 64;

  const int lj = lane >> 3, lr = lane & 7;
  int aRow[2];
  aRow[0] = wm + ((lj & 1) << 3) + lr;
  aRow[1] = aRow[0] + 16;
  const int aChO = lj >> 1;
  const int bKsub = ((lj & 1) << 3) + lr;  // k within 16-block
  const int bChHalf = lj >> 1;             // chunk bit from lane

  float acc[2][8][4];
#pragma unroll
  for (int i = 0; i < 2; i++)
#pragma unroll
    for (int j = 0; j < 8; j++)
#pragma unroll
      for (int q = 0; q < 4; q++) acc[i][j][q] = 0.f;

  auto load_stage = [&](int s, int kc) {
    uint32_t base = sb + s * STAGE_B;
    const __half* Ak = A + (size_t)kc * KTILE;
    const __half* Bk = B + (size_t)kc * KTILE * ldB + n0;
#pragma unroll
    for (int j = 0; j < 8; j++) {
      int idx = tid + j * 256;
      if (idx < 1024) {
        int c = idx & 7;
        int row = idx >> 3;
        cp_async16(base + swz(row * 128 + c * 16), Ak + (size_t)row * KK + c * 8);
      } else {
        int g = idx - 1024;          // 0..1023 = 64 k-rows x 16 n-chunks
        int row = g >> 4;            // k-row
        int ch = g & 15;             // n-chunk (8 halfs)
        int panel = ch >> 3, pc = ch & 7;
        cp_async16(base + A_TILE_B + panel * 8192 + swz(row * 128 + pc * 16),
                   Bk + (size_t)row * ldB + ch * 8);
      }
    }
  };

  auto compute_stage = [&](int s) {
    uint32_t abase = sb + s * STAGE_B;
    uint32_t bbase = abase + A_TILE_B + (wn >> 6) * 8192;  // warp's panel
#pragma unroll
    for (int ks = 0; ks < 4; ks++) {
      const int kc2 = ks * 2;
      uint32_t a[2][4], b[4][4];
#pragma unroll
      for (int mt = 0; mt < 2; mt++) {
        uint32_t addr = abase + aRow[mt] * 128 + (((kc2 + aChO) ^ (aRow[mt] & 7)) << 4);
        ldmatrix_x4(a[mt][0], a[mt][1], a[mt][2], a[mt][3], addr);
      }
      int krow = ks * 16 + bKsub;
#pragma unroll
      for (int p = 0; p < 4; p++) {
        int chunk = p * 2 + bChHalf;
        uint32_t addr = bbase + krow * 128 + ((chunk ^ (krow & 7)) << 4);
        ldmatrix_x4t(b[p][0], b[p][1], b[p][2], b[p][3], addr);
      }
#pragma unroll
      for (int mt = 0; mt < 2; mt++)
#pragma unroll
        for (int nt = 0; nt < 8; nt++) {
          uint32_t b0 = b[nt >> 1][(nt & 1) << 1];
          uint32_t b1 = b[nt >> 1][((nt & 1) << 1) + 1];
          mma16816(acc[mt][nt], a[mt][0], a[mt][1], a[mt][2], a[mt][3], b0, b1);
        }
    }
  };

#pragma unroll
  for (int s = 0; s < STAGES - 1; s++) {
    load_stage(s, kOff + s);
    asm volatile("cp.async.commit_group;" ::: "memory");
  }
  for (int it = 0; it < kIters; ++it) {
    int s = it & (STAGES - 1);
    asm volatile("cp.async.wait_group %0;" :: "n"(STAGES - 2) : "memory");
    __syncthreads();
    int pf = it + STAGES - 1;
    if (pf < kIters) load_stage(pf & (STAGES - 1), kOff + pf);
    asm volatile("cp.async.commit_group;" ::: "memory");
    compute_stage(s);
  }

  float* C = Cp + (size_t)blockIdx.y * slabStride;
  const int g = lane >> 2, tg = lane & 3;
#pragma unroll
  for (int mt = 0; mt < 2; mt++)
#pragma unroll
    for (int nt = 0; nt < 8; nt++) {
      int row0 = wm + mt * 16 + g;
      int col0 = n0 + wn + nt * 8 + tg * 2;
      *(float2*)(C + (size_t)row0 * ldC + col0) =
          make_float2(acc[mt][nt][0], acc[mt][nt][1]);
      *(float2*)(C + (size_t)(row0 + 8) * ldC + col0) =
          make_float2(acc[mt][nt][2], acc[mt][nt][3]);
    }
}

// ---------------- combine kernels ----------------
// Tbh = fp16(P0 + P1)
__global__ void k_comb_h(const float* __restrict__ P, __half* __restrict__ Out) {
  size_t i = ((size_t)blockIdx.x * blockDim.x + threadIdx.x) * 4;
  const float4 a = *(const float4*)(P + i);
  const float4 b = *(const float4*)(P + (size_t)DD * NN + i);
  uint2 o;
  o.x = h2u(__floats2half2_rn(a.x + b.x, a.y + b.y));
  o.y = h2u(__floats2half2_rn(a.z + b.z, a.w + b.w));
  *(uint2*)(Out + i) = o;
}

// Xh = LN_cols(P0 + P1) over the 128 rows
__global__ void k_comb_ln(const float* __restrict__ P, const float* __restrict__ gam,
                          const float* __restrict__ bet, __half* __restrict__ Xh) {
  __shared__ float sg[DD], sb[DD];
  if (threadIdx.x < DD) {
    sg[threadIdx.x] = gam[threadIdx.x];
    sb[threadIdx.x] = bet[threadIdx.x];
  }
  __syncthreads();
  int j = blockIdx.x * blockDim.x + threadIdx.x;
  const float* P1 = P + (size_t)DD * NN;
  float s = 0.f, sq = 0.f;
#pragma unroll 8
  for (int d = 0; d < DD; ++d) {
    float v = P[(size_t)d * NN + j] + P1[(size_t)d * NN + j];
    s += v; sq += v * v;
  }
  float mean = s * (1.0f / DD);
  float var = sq * (1.0f / DD) - mean * mean;
  float r = rsqrtf(var + LN_EPS);
#pragma unroll 8
  for (int d = 0; d < DD; ++d) {
    float v = P[(size_t)d * NN + j] + P1[(size_t)d * NN + j];
    Xh[(size_t)d * NN + j] = __float2half((v - mean) * r * sg[d] + sb[d]);
  }
}

// ---------------- conversion / aux kernels ----------------
__global__ void k_convT(const float* __restrict__ T, __half* __restrict__ Th) {
  size_t i = (size_t)blockIdx.x * blockDim.x + threadIdx.x;
  size_t n8 = (size_t)NN * NN / 8;
  const float4* src = (const float4*)T;
  uint4* dst = (uint4*)Th;
  for (size_t j = i; j < n8; j += (size_t)gridDim.x * blockDim.x) {
    float4 a = __ldcs(src + 2 * j), b = __ldcs(src + 2 * j + 1);
    uint4 o;
    o.x = h2u(__floats2half2_rn(a.x, a.y));
    o.y = h2u(__floats2half2_rn(a.z, a.w));
    o.z = h2u(__floats2half2_rn(b.x, b.y));
    o.w = h2u(__floats2half2_rn(b.z, b.w));
    dst[j] = o;
  }
}

__global__ void k_conv_x0(const float* __restrict__ x0, __half* __restrict__ Xh) {
  __shared__ float t[32][33];
  int d0 = blockIdx.x << 5, n0 = blockIdx.y << 5;
  int x = threadIdx.x, y = threadIdx.y;
#pragma unroll
  for (int i = 0; i < 32; i += 8)
    t[y + i][x] = x0[(size_t)(n0 + y + i) * DD + d0 + x];
  __syncthreads();
#pragma unroll
  for (int i = 0; i < 32; i += 8)
    Xh[(size_t)(d0 + y + i) * NN + n0 + x] = __float2half(t[x][y + i]);
}

// h [N,E] int32 -> hH fp16 (streaming) + counts
__global__ void k_conv_h(const int* __restrict__ h, __half* __restrict__ hH,
                         float* __restrict__ counts) {
  int e0 = blockIdx.x * 1024 + threadIdx.x * 4;
  int n0 = blockIdx.y * 16;
  float cnt0 = 0.f, cnt1 = 0.f, cnt2 = 0.f, cnt3 = 0.f;
#pragma unroll 4
  for (int r = 0; r < 16; r++) {
    int4 v = __ldcs((const int4*)(h + (size_t)(n0 + r) * EE + e0));
    float f0 = (v.x > 0) ? 1.f : 0.f, f1 = (v.y > 0) ? 1.f : 0.f;
    float f2 = (v.z > 0) ? 1.f : 0.f, f3 = (v.w > 0) ? 1.f : 0.f;
    uint2 o;
    o.x = h2u(__floats2half2_rn(f0, f1));
    o.y = h2u(__floats2half2_rn(f2, f3));
    *(uint2*)(hH + (size_t)(n0 + r) * EE + e0) = o;
    cnt0 += f0; cnt1 += f1; cnt2 += f2; cnt3 += f3;
  }
  atomicAdd(&counts[e0], cnt0);
  atomicAdd(&counts[e0 + 1], cnt1);
  atomicAdd(&counts[e0 + 2], cnt2);
  atomicAdd(&counts[e0 + 3], cnt3);
}

__global__ void k_zero(float* __restrict__ p, int n) {
  int i = blockIdx.x * blockDim.x + threadIdx.x;
  if (i < n) p[i] = 0.0f;
}

// max over e of (S0+S1+S2+S3)/counts per d
__global__ void k_final_max(const float* __restrict__ S, const float* __restrict__ counts,
                            float* __restrict__ out) {
  int d = blockIdx.x;
  const size_t stride = (size_t)DD * EE;
  const float* S0 = S + (size_t)d * EE;
  float m = -3.402823466e38f;
  for (int e = threadIdx.x; e < EE; e += blockDim.x) {
    float v = S0[e] + S0[stride + e] + S0[2 * stride + e] + S0[3 * stride + e];
    m = fmaxf(m, v / counts[e]);
  }
#pragma unroll
  for (int o = 16; o > 0; o >>= 1) m = fmaxf(m, __shfl_xor_sync(0xffffffffu, m, o));
  __shared__ float red[4];
  int lane = threadIdx.x & 31, w = threadIdx.x >> 5;
  if (lane == 0) red[w] = m;
  __syncthreads();
  if (threadIdx.x == 0)
    out[d] = fmaxf(fmaxf(red[0], red[1]), fmaxf(red[2], red[3]));
}

// ---------------- launch ----------------
extern "C" void kernel_launch(void* const* d_in, const int* in_sizes, int n_in,
                              void* d_out, int out_size) {
  const float* x0  = (const float*)d_in[0];  // [8192,128]
  const float* T   = (const float*)d_in[1];  // [8192,8192]
  const float* gam = (const float*)d_in[2];  // [128]
  const float* bet = (const float*)d_in[3];  // [128]
  const int*   h   = (const int*)d_in[4];    // [8192,4096]
  float* out = (float*)d_out;                // [128]

  __half *Th, *hH, *Xh, *Tbh;
  float *P, *S, *counts;
  cudaGetSymbolAddress((void**)&Th,  g_Th);
  cudaGetSymbolAddress((void**)&hH,  g_hH);
  cudaGetSymbolAddress((void**)&Xh,  g_Xh);
  cudaGetSymbolAddress((void**)&Tbh, g_Tbh);
  cudaGetSymbolAddress((void**)&P,   g_P);
  cudaGetSymbolAddress((void**)&S,   g_S);
  cudaGetSymbolAddress((void**)&counts, g_counts);

  cudaFuncSetAttribute(gemm_nt2, cudaFuncAttributeMaxDynamicSharedMemorySize, GEMM_SMEM);
  cudaFuncSetAttribute(gemm_tn2, cudaFuncAttributeMaxDynamicSharedMemorySize, GEMM_SMEM);

  k_convT<<<4096, 256>>>(T, Th);
  k_conv_x0<<<dim3(DD / 32, NN / 32), dim3(32, 8)>>>(x0, Xh);
  k_zero<<<(EE + 255) / 256, 256>>>(counts, EE);
  k_conv_h<<<dim3(EE / 1024, NN / 16), 256>>>(h, hH, counts);

  const size_t slabNN = (size_t)DD * NN;
  const size_t slabEE = (size_t)DD * EE;
  for (int l = 0; l < 3; ++l) {  // num_layers fixed at 3 by setup_inputs
    // t^T = (T x)^T : B = Th K-major, split-K=2
    gemm_nt2<<<dim3(NN / 128, 2), 256, GEMM_SMEM>>>(Xh, Th, 64, P, NN, slabNN);
    k_comb_h<<<(int)(slabNN / 1024), 256>>>(P, Tbh);
    // x^T = (T^T t)^T : B = Th as [k][n] (trans), split-K=2, then LN-combine
    gemm_tn2<<<dim3(NN / 128, 2), 256, GEMM_SMEM>>>(Tbh, Th, NN, 64, P, NN, slabNN);
    k_comb_ln<<<NN / 256, 256>>>(P, gam, bet, Xh);
  }
  // sums^T = x^T @ h : B = hH [n][e] (trans), split-K=4
  gemm_tn2<<<dim3(EE / 128, 4), 256, GEMM_SMEM>>>(Xh, hH, EE, 32, S, EE, slabEE);
  k_final_max<<<DD, 128>>>(S, counts, out);
}

// round 6
// speedup vs baseline: 1.0202x; 1.0202x over previous
#include <cuda_runtime.h>
#include <cuda_fp16.h>
#include <cstdint>

// Problem sizes (fixed by setup_inputs)
#define NN 8192   // nodes
#define DD 128    // embedding dim
#define EE 4096   // hyperedges
#define KK 8192   // reduction dim of the big GEMMs
#define LN_EPS 1e-5f

// ---------------- GEMM config (round-4 structure: 128x64 tile) ---------------
#define KTILE 64                       // halfs per k-chunk = 128 B rows
#define NTILE 64
#define STAGES 4
#define NIT (KK / KTILE)               // 128 k-iterations (full K)
#define A_STAGE_BYTES (128 * 128)      // 16 KB
#define B_STAGE_BYTES (64 * 128)       // 8 KB
#define STAGE_BYTES (A_STAGE_BYTES + B_STAGE_BYTES)
#define GEMM_SMEM (STAGES * STAGE_BYTES)  // 96 KB

// ---------------- scratch (device globals; no allocation allowed) ------------
__device__ __half g_Th [(size_t)NN * NN];     // T fp16             128 MB
__device__ __half g_hH [(size_t)NN * EE];     // h fp16 [N,E]        64 MB
__device__ __half g_Xh [(size_t)DD * NN];     // x^T fp16             2 MB
__device__ __half g_Tbh[(size_t)DD * NN];     // t^T fp16             2 MB
__device__ float  g_S  [(size_t)2 * DD * EE]; // final partials       4 MB
__device__ float  g_counts[EE];

// ---------------- helpers ----------------
__device__ __forceinline__ uint32_t h2u(__half2 h) {
  uint32_t u;
  *reinterpret_cast<__half2*>(&u) = h;
  return u;
}
__device__ __forceinline__ uint32_t smem_u32(const void* p) {
  uint32_t a;
  asm("{ .reg .u64 t; cvta.to.shared.u64 t, %1; cvt.u32.u64 %0, t; }" : "=r"(a) : "l"(p));
  return a;
}
__device__ __forceinline__ uint32_t swz(uint32_t b) { return b ^ ((b >> 3) & 0x70); }
__device__ __forceinline__ void cp_async16(uint32_t dst, const void* src) {
  asm volatile("cp.async.cg.shared.global [%0], [%1], 16;" :: "r"(dst), "l"(src));
}
__device__ __forceinline__ void ldmatrix_x4(uint32_t& r0, uint32_t& r1, uint32_t& r2,
                                            uint32_t& r3, uint32_t addr) {
  asm volatile("ldmatrix.sync.aligned.m8n8.x4.shared.b16 {%0,%1,%2,%3}, [%4];"
               : "=r"(r0), "=r"(r1), "=r"(r2), "=r"(r3) : "r"(addr));
}
__device__ __forceinline__ void ldmatrix_x4t(uint32_t& r0, uint32_t& r1, uint32_t& r2,
                                             uint32_t& r3, uint32_t addr) {
  asm volatile("ldmatrix.sync.aligned.m8n8.x4.trans.shared.b16 {%0,%1,%2,%3}, [%4];"
               : "=r"(r0), "=r"(r1), "=r"(r2), "=r"(r3) : "r"(addr));
}
__device__ __forceinline__ void mma16816(float* c, uint32_t a0, uint32_t a1, uint32_t a2,
                                         uint32_t a3, uint32_t b0, uint32_t b1) {
  asm volatile(
      "mma.sync.aligned.m16n8k16.row.col.f32.f16.f16.f32 "
      "{%0,%1,%2,%3}, {%4,%5,%6,%7}, {%8,%9}, {%0,%1,%2,%3};"
      : "+f"(c[0]), "+f"(c[1]), "+f"(c[2]), "+f"(c[3])
      : "r"(a0), "r"(a1), "r"(a2), "r"(a3), "r"(b0), "r"(b1));
}

// ============ GEMM 1: C[128,Ntot] = A[128,K] @ B[Ntot,K]^T, B K-major =========
__global__ __launch_bounds__(256, 1)
void gemm_nt(const __half* __restrict__ A, const __half* __restrict__ B,
             __half* __restrict__ C, int ldC) {
  extern __shared__ char smem[];
  uint32_t sb = smem_u32(smem);
  const int tid = threadIdx.x;
  const int wid = tid >> 5, lane = tid & 31;
  const int n0 = blockIdx.x * NTILE;
  const int wm = (wid & 3) * 32;
  const int wn = (wid >> 2) * 32;

  const int lj = lane >> 3, lr = lane & 7;
  int aRow[2], bRow[2];
  aRow[0] = wm + ((lj & 1) << 3) + lr;
  aRow[1] = aRow[0] + 16;
  const int aChO = lj >> 1;
  bRow[0] = wn + ((lj >> 1) << 3) + lr;
  bRow[1] = bRow[0] + 16;
  const int bChO = lj & 1;

  float acc[2][4][4];
#pragma unroll
  for (int i = 0; i < 2; i++)
#pragma unroll
    for (int j = 0; j < 4; j++)
#pragma unroll
      for (int q = 0; q < 4; q++) acc[i][j][q] = 0.f;

  auto load_stage = [&](int s, int kc) {
    uint32_t base = sb + s * STAGE_BYTES;
    const __half* Ak = A + (size_t)kc * KTILE;
    const __half* Bk = B + (size_t)n0 * KK + (size_t)kc * KTILE;
#pragma unroll
    for (int j = 0; j < 6; j++) {
      int idx = tid + j * 256;
      int c = idx & 7;
      if (idx < 1024) {
        int row = idx >> 3;
        cp_async16(base + swz(row * 128 + c * 16), Ak + (size_t)row * KK + c * 8);
      } else {
        int row = (idx - 1024) >> 3;
        cp_async16(base + A_STAGE_BYTES + swz(row * 128 + c * 16),
                   Bk + (size_t)row * KK + c * 8);
      }
    }
  };

  // ks-pipelined compute: prefetch ldmatrix for ks+1 while MMAs of ks run
  auto compute_stage = [&](int s) {
    uint32_t abase = sb + s * STAGE_BYTES;
    uint32_t bbase = abase + A_STAGE_BYTES;
    uint32_t a[2][2][4], b[2][2][4];
    auto ldm = [&](int ks, int buf) {
      const int kc2 = ks * 2;
#pragma unroll
      for (int mt = 0; mt < 2; mt++) {
        uint32_t addr = abase + aRow[mt] * 128 + (((kc2 + aChO) ^ (aRow[mt] & 7)) << 4);
        ldmatrix_x4(a[buf][mt][0], a[buf][mt][1], a[buf][mt][2], a[buf][mt][3], addr);
      }
#pragma unroll
      for (int p = 0; p < 2; p++) {
        uint32_t addr = bbase + bRow[p] * 128 + (((kc2 + bChO) ^ (bRow[p] & 7)) << 4);
        ldmatrix_x4(b[buf][p][0], b[buf][p][1], b[buf][p][2], b[buf][p][3], addr);
      }
    };
    ldm(0, 0);
#pragma unroll
    for (int ks = 0; ks < 4; ks++) {
      int buf = ks & 1;
      if (ks < 3) ldm(ks + 1, buf ^ 1);
#pragma unroll
      for (int mt = 0; mt < 2; mt++)
#pragma unroll
        for (int nt = 0; nt < 4; nt++) {
          uint32_t b0 = b[buf][nt >> 1][(nt & 1) ? 2 : 0];
          uint32_t b1 = b[buf][nt >> 1][(nt & 1) ? 3 : 1];
          mma16816(acc[mt][nt], a[buf][mt][0], a[buf][mt][1], a[buf][mt][2],
                   a[buf][mt][3], b0, b1);
        }
    }
  };

#pragma unroll
  for (int s = 0; s < STAGES - 1; s++) {
    load_stage(s, s);
    asm volatile("cp.async.commit_group;" ::: "memory");
  }
  for (int it = 0; it < NIT; ++it) {
    int s = it & (STAGES - 1);
    asm volatile("cp.async.wait_group %0;" :: "n"(STAGES - 2) : "memory");
    __syncthreads();
    int pf = it + STAGES - 1;
    if (pf < NIT) load_stage(pf & (STAGES - 1), pf);
    asm volatile("cp.async.commit_group;" ::: "memory");
    compute_stage(s);
  }

  const int g = lane >> 2, tg = lane & 3;
#pragma unroll
  for (int mt = 0; mt < 2; mt++)
#pragma unroll
    for (int nt = 0; nt < 4; nt++) {
      int row0 = wm + mt * 16 + g;
      int col0 = n0 + wn + nt * 8 + tg * 2;
      __half2 h0 = __floats2half2_rn(acc[mt][nt][0], acc[mt][nt][1]);
      __half2 h1 = __floats2half2_rn(acc[mt][nt][2], acc[mt][nt][3]);
      *(__half2*)(C + (size_t)row0 * ldC + col0) = h0;
      *(__half2*)(C + (size_t)(row0 + 8) * ldC + col0) = h1;
    }
}

// ===== GEMM 2: C[128,Ntot] = A[128,K] @ B[K,Ntot], B N-major (trans-ldmatrix) =
// LNF=1: fused column LayerNorm, fp16 out. LNF=0: fp32 partial slabs (split-K).
template <int LNF>
__global__ __launch_bounds__(256, 1)
void gemm_tn(const __half* __restrict__ A, const __half* __restrict__ B, int ldB,
             int kIters, void* __restrict__ Cout, int ldC,
             const float* __restrict__ gam, const float* __restrict__ bet) {
  extern __shared__ char smem[];
  uint32_t sb = smem_u32(smem);
  const int tid = threadIdx.x;
  const int wid = tid >> 5, lane = tid & 31;
  const int n0 = blockIdx.x * NTILE;
  const int kOff = blockIdx.y * kIters;
  const int wm = (wid & 3) * 32;
  const int wn = (wid >> 2) * 32;

  const int lj = lane >> 3, lr = lane & 7;
  int aRow[2];
  aRow[0] = wm + ((lj & 1) << 3) + lr;
  aRow[1] = aRow[0] + 16;
  const int aChO = lj >> 1;
  const int bKsub = ((lj & 1) << 3) + lr;
  const int bChSub = (wn >> 3) + (lj >> 1);

  float acc[2][4][4];
#pragma unroll
  for (int i = 0; i < 2; i++)
#pragma unroll
    for (int j = 0; j < 4; j++)
#pragma unroll
      for (int q = 0; q < 4; q++) acc[i][j][q] = 0.f;

  auto load_stage = [&](int s, int kc) {
    uint32_t base = sb + s * STAGE_BYTES;
    const __half* Ak = A + (size_t)kc * KTILE;
    const __half* Bk = B + (size_t)kc * KTILE * ldB + n0;
#pragma unroll
    for (int j = 0; j < 6; j++) {
      int idx = tid + j * 256;
      int c = idx & 7;
      if (idx < 1024) {
        int row = idx >> 3;
        cp_async16(base + swz(row * 128 + c * 16), Ak + (size_t)row * KK + c * 8);
      } else {
        int row = (idx - 1024) >> 3;
        cp_async16(base + A_STAGE_BYTES + swz(row * 128 + c * 16),
                   Bk + (size_t)row * ldB + c * 8);
      }
    }
  };

  auto compute_stage = [&](int s) {
    uint32_t abase = sb + s * STAGE_BYTES;
    uint32_t bbase = abase + A_STAGE_BYTES;
    uint32_t a[2][2][4], b[2][2][4];
    auto ldm = [&](int ks, int buf) {
      const int kc2 = ks * 2;
#pragma unroll
      for (int mt = 0; mt < 2; mt++) {
        uint32_t addr = abase + aRow[mt] * 128 + (((kc2 + aChO) ^ (aRow[mt] & 7)) << 4);
        ldmatrix_x4(a[buf][mt][0], a[buf][mt][1], a[buf][mt][2], a[buf][mt][3], addr);
      }
      int krow = ks * 16 + bKsub;
#pragma unroll
      for (int p = 0; p < 2; p++) {
        int chunk = bChSub + p * 2;
        uint32_t addr = bbase + krow * 128 + ((chunk ^ (krow & 7)) << 4);
        ldmatrix_x4t(b[buf][p][0], b[buf][p][1], b[buf][p][2], b[buf][p][3], addr);
      }
    };
    ldm(0, 0);
#pragma unroll
    for (int ks = 0; ks < 4; ks++) {
      int buf = ks & 1;
      if (ks < 3) ldm(ks + 1, buf ^ 1);
#pragma unroll
      for (int mt = 0; mt < 2; mt++)
#pragma unroll
        for (int nt = 0; nt < 4; nt++) {
          uint32_t b0 = b[buf][nt >> 1][(nt & 1) << 1];
          uint32_t b1 = b[buf][nt >> 1][((nt & 1) << 1) + 1];
          mma16816(acc[mt][nt], a[buf][mt][0], a[buf][mt][1], a[buf][mt][2],
                   a[buf][mt][3], b0, b1);
        }
    }
  };

#pragma unroll
  for (int s = 0; s < STAGES - 1; s++) {
    load_stage(s, kOff + s);
    asm volatile("cp.async.commit_group;" ::: "memory");
  }
  for (int it = 0; it < kIters; ++it) {
    int s = it & (STAGES - 1);
    asm volatile("cp.async.wait_group %0;" :: "n"(STAGES - 2) : "memory");
    __syncthreads();
    int pf = it + STAGES - 1;
    if (pf < kIters) load_stage(pf & (STAGES - 1), kOff + pf);
    asm volatile("cp.async.commit_group;" ::: "memory");
    compute_stage(s);
  }

  const int g = lane >> 2, tg = lane & 3;

  if (LNF) {
    asm volatile("cp.async.wait_group 0;" ::: "memory");
    __syncthreads();
    float* s_sum = reinterpret_cast<float*>(smem);          // [4][64]
    float* s_sq  = reinterpret_cast<float*>(smem) + 256;    // [4][64]

    float ps[4][2], pq[4][2];
#pragma unroll
    for (int nt = 0; nt < 4; nt++)
#pragma unroll
      for (int j = 0; j < 2; j++) {
        float sv = 0.f, qv = 0.f;
#pragma unroll
        for (int mt = 0; mt < 2; mt++) {
          float v0 = acc[mt][nt][j], v1 = acc[mt][nt][j + 2];
          sv += v0 + v1;
          qv += v0 * v0 + v1 * v1;
        }
#pragma unroll
        for (int o = 4; o < 32; o <<= 1) {
          sv += __shfl_xor_sync(0xffffffffu, sv, o);
          qv += __shfl_xor_sync(0xffffffffu, qv, o);
        }
        ps[nt][j] = sv;
        pq[nt][j] = qv;
      }
    if (g == 0) {
      int mw = wid & 3;
#pragma unroll
      for (int nt = 0; nt < 4; nt++)
#pragma unroll
        for (int j = 0; j < 2; j++) {
          int col = wn + nt * 8 + tg * 2 + j;
          s_sum[mw * 64 + col] = ps[nt][j];
          s_sq[mw * 64 + col] = pq[nt][j];
        }
    }
    __syncthreads();

    float mean[4][2], rinv[4][2];
#pragma unroll
    for (int nt = 0; nt < 4; nt++)
#pragma unroll
      for (int j = 0; j < 2; j++) {
        int col = wn + nt * 8 + tg * 2 + j;
        float tot = s_sum[col] + s_sum[64 + col] + s_sum[128 + col] + s_sum[192 + col];
        float tq  = s_sq[col] + s_sq[64 + col] + s_sq[128 + col] + s_sq[192 + col];
        float m = tot * (1.0f / DD);
        float var = tq * (1.0f / DD) - m * m;
        mean[nt][j] = m;
        rinv[nt][j] = rsqrtf(var + LN_EPS);
      }

    __half* C = (__half*)Cout;
#pragma unroll
    for (int mt = 0; mt < 2; mt++) {
      int r0 = wm + mt * 16 + g;
      float g0 = gam[r0], b0 = bet[r0];
      float g1 = gam[r0 + 8], b1 = bet[r0 + 8];
#pragma unroll
      for (int nt = 0; nt < 4; nt++) {
        int col0 = n0 + wn + nt * 8 + tg * 2;
        float y00 = (acc[mt][nt][0] - mean[nt][0]) * rinv[nt][0] * g0 + b0;
        float y01 = (acc[mt][nt][1] - mean[nt][1]) * rinv[nt][1] * g0 + b0;
        float y10 = (acc[mt][nt][2] - mean[nt][0]) * rinv[nt][0] * g1 + b1;
        float y11 = (acc[mt][nt][3] - mean[nt][1]) * rinv[nt][1] * g1 + b1;
        *(__half2*)(C + (size_t)r0 * ldC + col0) = __floats2half2_rn(y00, y01);
        *(__half2*)(C + (size_t)(r0 + 8) * ldC + col0) = __floats2half2_rn(y10, y11);
      }
    }
  } else {
    float* C = (float*)Cout + (size_t)blockIdx.y * DD * EE;
#pragma unroll
    for (int mt = 0; mt < 2; mt++)
#pragma unroll
      for (int nt = 0; nt < 4; nt++) {
        int row0 = wm + mt * 16 + g;
        int col0 = n0 + wn + nt * 8 + tg * 2;
        *(float2*)(C + (size_t)row0 * ldC + col0) =
            make_float2(acc[mt][nt][0], acc[mt][nt][1]);
        *(float2*)(C + (size_t)(row0 + 8) * ldC + col0) =
            make_float2(acc[mt][nt][2], acc[mt][nt][3]);
      }
  }
}

// ---------------- conversion / aux kernels ----------------
__global__ void k_convT(const float* __restrict__ T, __half* __restrict__ Th) {
  size_t i = (size_t)blockIdx.x * blockDim.x + threadIdx.x;
  size_t n8 = (size_t)NN * NN / 8;
  const float4* src = (const float4*)T;
  uint4* dst = (uint4*)Th;
  for (size_t j = i; j < n8; j += (size_t)gridDim.x * blockDim.x) {
    float4 a = __ldcs(src + 2 * j), b = __ldcs(src + 2 * j + 1);
    uint4 o;
    o.x = h2u(__floats2half2_rn(a.x, a.y));
    o.y = h2u(__floats2half2_rn(a.z, a.w));
    o.z = h2u(__floats2half2_rn(b.x, b.y));
    o.w = h2u(__floats2half2_rn(b.z, b.w));
    dst[j] = o;
  }
}

__global__ void k_conv_x0(const float* __restrict__ x0, __half* __restrict__ Xh) {
  __shared__ float t[32][33];
  int d0 = blockIdx.x << 5, n0 = blockIdx.y << 5;
  int x = threadIdx.x, y = threadIdx.y;
#pragma unroll
  for (int i = 0; i < 32; i += 8)
    t[y + i][x] = x0[(size_t)(n0 + y + i) * DD + d0 + x];
  __syncthreads();
#pragma unroll
  for (int i = 0; i < 32; i += 8)
    Xh[(size_t)(d0 + y + i) * NN + n0 + x] = __float2half(t[x][y + i]);
}

// h [N,E] int32 -> hH fp16 (streaming) + counts ; grid (4, 128), unroll 8
__global__ void k_conv_h(const int* __restrict__ h, __half* __restrict__ hH,
                         float* __restrict__ counts) {
  int e0 = blockIdx.x * 1024 + threadIdx.x * 4;
  int n0 = blockIdx.y * 64;
  float cnt0 = 0.f, cnt1 = 0.f, cnt2 = 0.f, cnt3 = 0.f;
#pragma unroll 8
  for (int r = 0; r < 64; r++) {
    int4 v = __ldcs((const int4*)(h + (size_t)(n0 + r) * EE + e0));
    float f0 = (v.x > 0) ? 1.f : 0.f, f1 = (v.y > 0) ? 1.f : 0.f;
    float f2 = (v.z > 0) ? 1.f : 0.f, f3 = (v.w > 0) ? 1.f : 0.f;
    uint2 o;
    o.x = h2u(__floats2half2_rn(f0, f1));
    o.y = h2u(__floats2half2_rn(f2, f3));
    *(uint2*)(hH + (size_t)(n0 + r) * EE + e0) = o;
    cnt0 += f0; cnt1 += f1; cnt2 += f2; cnt3 += f3;
  }
  atomicAdd(&counts[e0], cnt0);
  atomicAdd(&counts[e0 + 1], cnt1);
  atomicAdd(&counts[e0 + 2], cnt2);
  atomicAdd(&counts[e0 + 3], cnt3);
}

__global__ void k_zero(float* __restrict__ p, int n) {
  int i = blockIdx.x * blockDim.x + threadIdx.x;
  if (i < n) p[i] = 0.0f;
}

__global__ void k_final_max(const float* __restrict__ S, const float* __restrict__ counts,
                            float* __restrict__ out) {
  int d = blockIdx.x;
  const float* S0 = S + (size_t)d * EE;
  const float* S1 = S + (size_t)DD * EE + (size_t)d * EE;
  float m = -3.402823466e38f;
  for (int e = threadIdx.x; e < EE; e += blockDim.x)
    m = fmaxf(m, (S0[e] + S1[e]) / counts[e]);
#pragma unroll
  for (int o = 16; o > 0; o >>= 1) m = fmaxf(m, __shfl_xor_sync(0xffffffffu, m, o));
  __shared__ float red[4];
  int lane = threadIdx.x & 31, w = threadIdx.x >> 5;
  if (lane == 0) red[w] = m;
  __syncthreads();
  if (threadIdx.x == 0)
    out[d] = fmaxf(fmaxf(red[0], red[1]), fmaxf(red[2], red[3]));
}

// ---------------- launch ----------------
extern "C" void kernel_launch(void* const* d_in, const int* in_sizes, int n_in,
                              void* d_out, int out_size) {
  const float* x0  = (const float*)d_in[0];  // [8192,128]
  const float* T   = (const float*)d_in[1];  // [8192,8192]
  const float* gam = (const float*)d_in[2];  // [128]
  const float* bet = (const float*)d_in[3];  // [128]
  const int*   h   = (const int*)d_in[4];    // [8192,4096]
  float* out = (float*)d_out;                // [128]

  __half *Th, *hH, *Xh, *Tbh;
  float *S, *counts;
  cudaGetSymbolAddress((void**)&Th,  g_Th);
  cudaGetSymbolAddress((void**)&hH,  g_hH);
  cudaGetSymbolAddress((void**)&Xh,  g_Xh);
  cudaGetSymbolAddress((void**)&Tbh, g_Tbh);
  cudaGetSymbolAddress((void**)&S,   g_S);
  cudaGetSymbolAddress((void**)&counts, g_counts);

  cudaFuncSetAttribute(gemm_nt, cudaFuncAttributeMaxDynamicSharedMemorySize, GEMM_SMEM);
  cudaFuncSetAttribute(gemm_tn<0>, cudaFuncAttributeMaxDynamicSharedMemorySize, GEMM_SMEM);
  cudaFuncSetAttribute(gemm_tn<1>, cudaFuncAttributeMaxDynamicSharedMemorySize, GEMM_SMEM);

  k_convT<<<4096, 256>>>(T, Th);
  k_conv_x0<<<dim3(DD / 32, NN / 32), dim3(32, 8)>>>(x0, Xh);
  k_zero<<<(EE + 255) / 256, 256>>>(counts, EE);
  k_conv_h<<<dim3(EE / 1024, NN / 64), 256>>>(h, hH, counts);

  for (int l = 0; l < 3; ++l) {  // num_layers fixed at 3 by setup_inputs
    gemm_nt<<<NN / NTILE, 256, GEMM_SMEM>>>(Xh, Th, Tbh, NN);
    gemm_tn<1><<<dim3(NN / NTILE, 1), 256, GEMM_SMEM>>>(
        Tbh, Th, NN, NIT, Xh, NN, gam, bet);
  }
  gemm_tn<0><<<dim3(EE / NTILE, 2), 256, GEMM_SMEM>>>(
      Xh, hH, EE, NIT / 2, S, EE, gam, bet);
  k_final_max<<<DD, 128>>>(S, counts, out);
}